// round 4
// baseline (speedup 1.0000x reference)
#include <cuda_runtime.h>
#include <cstdint>

#define NN    50000
#define EE    800000
#define FIN   80
#define HH    4
#define CC    96
#define DD    384
#define NCLS  20

// ---------------- device scratch (no allocations allowed) ----------------
__device__ float g_xs[(size_t)NN * DD];
__device__ float g_xd[(size_t)NN * DD];
__device__ float g_h [(size_t)NN * DD];
__device__ float g_t1[(size_t)NN * CC];
__device__ int   g_off[NN + 1];
__device__ int   g_cur[NN];
__device__ int   g_eid[EE];
__device__ int   g_csrc[EE];

// ---------------- CSR build ----------------
__global__ void hist_k(const int* __restrict__ dst, int* __restrict__ cnt) {
    int i = blockIdx.x * blockDim.x + threadIdx.x;
    if (i < EE) atomicAdd(&cnt[dst[i]], 1);
}

// warp-shuffle scan; writes exclusive offsets to off AND cur
__global__ void scan_k(const int* __restrict__ cnt, int* __restrict__ off,
                       int* __restrict__ cur) {
    __shared__ int wsums[32];
    __shared__ int carry_s;
    const int t = threadIdx.x, lane = t & 31, wp = t >> 5;
    if (t == 0) carry_s = 0;
    __syncthreads();
    for (int base = 0; base < NN; base += 1024) {
        int i = base + t;
        int v = (i < NN) ? cnt[i] : 0;
        int x = v;
#pragma unroll
        for (int o = 1; o < 32; o <<= 1) {
            int y = __shfl_up_sync(0xffffffffu, x, o);
            if (lane >= o) x += y;
        }
        if (lane == 31) wsums[wp] = x;
        __syncthreads();
        if (wp == 0) {
            int ws = wsums[lane];
#pragma unroll
            for (int o = 1; o < 32; o <<= 1) {
                int y = __shfl_up_sync(0xffffffffu, ws, o);
                if (lane >= o) ws += y;
            }
            wsums[lane] = ws;
        }
        __syncthreads();
        int add = (wp > 0) ? wsums[wp - 1] : 0;
        int excl = carry_s + x + add - v;
        if (i < NN) { off[i] = excl; cur[i] = excl; }
        int tot = wsums[31];
        __syncthreads();
        if (t == 0) carry_s += tot;
        __syncthreads();
    }
    if (t == 0) off[NN] = carry_s;
}

__global__ void scatter_k(const int* __restrict__ dst, int* __restrict__ cur,
                          int* __restrict__ eid) {
    int i = blockIdx.x * blockDim.x + threadIdx.x;
    if (i < EE) {
        int d = dst[i];
        int p = atomicAdd(&cur[d], 1);
        eid[p] = i;
    }
}

// deterministic order within segment (sort edge ids), then gather src
__global__ void sortsrc_k(const int* __restrict__ srcArr, const int* __restrict__ off,
                          int* __restrict__ eid, int* __restrict__ csrc) {
    int v = blockIdx.x * blockDim.x + threadIdx.x;
    if (v >= NN) return;
    int s = off[v], e = off[v + 1];
    for (int i = s + 1; i < e; i++) {
        int key = eid[i];
        int j = i - 1;
        while (j >= s && eid[j] > key) { eid[j + 1] = eid[j]; j--; }
        eid[j + 1] = key;
    }
    for (int i = s; i < e; i++) csrc[i] = srcArr[eid[i]];
}

// ---------------- tf32 tensor-core GEMM: C[M,N] = A[M,K] @ B[K,N] ----------------
// 128x128 CTA tile, 8 warps (64x32 warp tiles), BK=16, mma.m16n8k8.tf32.
// Double-buffered SMEM + software-pipelined global loads (1 barrier/iter).
__device__ __forceinline__ uint32_t f2tf32(float f) {
    uint32_t r;
    asm("cvt.rna.tf32.f32 %0, %1;" : "=r"(r) : "f"(f));
    return r;
}

__global__ __launch_bounds__(256) void gemm_tc(const float* __restrict__ A,
                                               const float* __restrict__ B,
                                               float* __restrict__ C,
                                               int M, int K, int N) {
    __shared__ uint32_t As[2][16][136];
    __shared__ uint32_t Bs[2][16][136];

    const int t    = threadIdx.x;
    const int lane = t & 31;
    const int w    = t >> 5;
    const int wm   = (w & 1) * 64;   // warp m offset
    const int wn   = (w >> 1) * 32;  // warp n offset
    const int g    = lane >> 2;      // 0..7
    const int tid4 = lane & 3;       // 0..3
    const int bm   = blockIdx.y * 128;
    const int bn   = blockIdx.x * 128;

    float acc[4][4][4];
#pragma unroll
    for (int i = 0; i < 4; i++)
#pragma unroll
        for (int j = 0; j < 4; j++)
#pragma unroll
            for (int r = 0; r < 4; r++) acc[i][j][r] = 0.f;

    // global-load mappings
    const int am  = t >> 2;          // 0..63 (+64 for second half)
    const int ak  = (t & 3) * 4;     // k quad
    const int bk  = t >> 5;          // 0..7 (+8)
    const int bn4 = (t & 31) * 4;    // n quad
    const int gn  = bn + bn4;

    const int KT = K >> 4;           // K multiple of 16
    float4 av[2], bv[2];

    // preload tile 0
#pragma unroll
    for (int p = 0; p < 2; p++) {
        int gm = bm + am + p * 64;
        av[p] = make_float4(0.f, 0.f, 0.f, 0.f);
        if (gm < M) av[p] = *(const float4*)(A + (size_t)gm * K + ak);
        bv[p] = make_float4(0.f, 0.f, 0.f, 0.f);
        if (gn < N) bv[p] = *(const float4*)(B + (size_t)(bk + p * 8) * N + gn);
    }

    for (int kt = 0; kt < KT; kt++) {
        const int buf = kt & 1;
        // store current tile (convert to tf32)
#pragma unroll
        for (int p = 0; p < 2; p++) {
            As[buf][ak + 0][am + p * 64] = f2tf32(av[p].x);
            As[buf][ak + 1][am + p * 64] = f2tf32(av[p].y);
            As[buf][ak + 2][am + p * 64] = f2tf32(av[p].z);
            As[buf][ak + 3][am + p * 64] = f2tf32(av[p].w);
            Bs[buf][bk + p * 8][bn4 + 0] = f2tf32(bv[p].x);
            Bs[buf][bk + p * 8][bn4 + 1] = f2tf32(bv[p].y);
            Bs[buf][bk + p * 8][bn4 + 2] = f2tf32(bv[p].z);
            Bs[buf][bk + p * 8][bn4 + 3] = f2tf32(bv[p].w);
        }
        // prefetch next tile (overlaps with this tile's MMAs)
        if (kt + 1 < KT) {
            const int k0 = (kt + 1) << 4;
#pragma unroll
            for (int p = 0; p < 2; p++) {
                int gm = bm + am + p * 64;
                av[p] = make_float4(0.f, 0.f, 0.f, 0.f);
                if (gm < M) av[p] = *(const float4*)(A + (size_t)gm * K + k0 + ak);
                bv[p] = make_float4(0.f, 0.f, 0.f, 0.f);
                if (gn < N) bv[p] = *(const float4*)(B + (size_t)(k0 + bk + p * 8) * N + gn);
            }
        }
        __syncthreads();

#pragma unroll
        for (int ks = 0; ks < 2; ks++) {
            const int kb = ks * 8;
            uint32_t af[4][4];
#pragma unroll
            for (int mt = 0; mt < 4; mt++) {
                int m = wm + mt * 16;
                af[mt][0] = As[buf][kb + tid4    ][m + g];
                af[mt][1] = As[buf][kb + tid4    ][m + g + 8];
                af[mt][2] = As[buf][kb + tid4 + 4][m + g];
                af[mt][3] = As[buf][kb + tid4 + 4][m + g + 8];
            }
            uint32_t bf[4][2];
#pragma unroll
            for (int nt = 0; nt < 4; nt++) {
                int n = wn + nt * 8;
                bf[nt][0] = Bs[buf][kb + tid4    ][n + g];
                bf[nt][1] = Bs[buf][kb + tid4 + 4][n + g];
            }
#pragma unroll
            for (int mt = 0; mt < 4; mt++)
#pragma unroll
                for (int nt = 0; nt < 4; nt++) {
                    float* c = acc[mt][nt];
                    asm volatile(
                        "mma.sync.aligned.m16n8k8.row.col.f32.tf32.tf32.f32 "
                        "{%0,%1,%2,%3}, {%4,%5,%6,%7}, {%8,%9}, {%0,%1,%2,%3};"
                        : "+f"(c[0]), "+f"(c[1]), "+f"(c[2]), "+f"(c[3])
                        : "r"(af[mt][0]), "r"(af[mt][1]), "r"(af[mt][2]), "r"(af[mt][3]),
                          "r"(bf[nt][0]), "r"(bf[nt][1]));
                }
        }
    }

    // epilogue
#pragma unroll
    for (int mt = 0; mt < 4; mt++) {
#pragma unroll
        for (int nt = 0; nt < 4; nt++) {
            int r0 = bm + wm + mt * 16 + g;
            int c  = bn + wn + nt * 8 + 2 * tid4;
            if (c < N) {
                if (r0 < M)
                    *(float2*)(C + (size_t)r0 * N + c) =
                        make_float2(acc[mt][nt][0], acc[mt][nt][1]);
                if (r0 + 8 < M)
                    *(float2*)(C + (size_t)(r0 + 8) * N + c) =
                        make_float2(acc[mt][nt][2], acc[mt][nt][3]);
            }
        }
    }
}

// ---------------- helpers ----------------
__device__ __forceinline__ float wsum(float v) {
#pragma unroll
    for (int o = 16; o; o >>= 1) v += __shfl_xor_sync(0xffffffffu, v, o);
    return v;
}

// ---------------- GATv2 layer: attention + softmax + aggregate + bias + LN + ELU
// one block (128 threads) per node; warp w = head w. Chunked (8 edges) scoring:
// the 8 score reductions are independent and pipeline; exp/rescale happen once
// per chunk against the chunk max, so the per-edge serial chain collapses.
#define CHK 8
__global__ __launch_bounds__(128) void gat_k(const float* __restrict__ xs,
                                             const float* __restrict__ xd,
                                             const float* __restrict__ att,
                                             const float* __restrict__ bias,
                                             const float* __restrict__ gamma,
                                             const float* __restrict__ beta,
                                             const int* __restrict__ off,
                                             const int* __restrict__ csrc,
                                             float* __restrict__ out) {
    const int node = blockIdx.x;
    const int w    = threadIdx.x >> 5;
    const int lane = threadIdx.x & 31;

    const float* ah = att + w * CC;
    const float a0 = ah[lane], a1 = ah[lane + 32], a2 = ah[lane + 64];

    const float* dr = xd + (size_t)node * DD + w * CC;
    const float d0 = dr[lane], d1 = dr[lane + 32], d2 = dr[lane + 64];

    const int s = off[node], e = off[node + 1];

    float mx = -3.0e38f, den = 0.f;
    float acc0 = 0.f, acc1 = 0.f, acc2 = 0.f;

    for (int j0 = s; j0 < e; j0 += CHK) {
        const int cnt = min(CHK, e - j0);
        float sv0[CHK], sv1[CHK], sv2[CHK], sc[CHK];

        // 1) gather src rows — 3*CHK independent 128B-coalesced loads (high MLP)
#pragma unroll
        for (int t = 0; t < CHK; t++) {
            if (t < cnt) {
                int sr = __ldg(&csrc[j0 + t]);
                const float* xr = xs + (size_t)sr * DD + w * CC;
                sv0[t] = xr[lane]; sv1[t] = xr[lane + 32]; sv2[t] = xr[lane + 64];
            }
        }
        // 2) scores — independent shuffle trees, pipelined
#pragma unroll
        for (int t = 0; t < CHK; t++) {
            if (t < cnt) {
                float m0 = sv0[t] + d0; m0 = (m0 > 0.f) ? m0 : 0.2f * m0;
                float m1 = sv1[t] + d1; m1 = (m1 > 0.f) ? m1 : 0.2f * m1;
                float m2 = sv2[t] + d2; m2 = (m2 > 0.f) ? m2 : 0.2f * m2;
                sc[t] = wsum(a0 * m0 + a1 * m1 + a2 * m2);
            }
        }
        // 3) chunk max + single rescale of running state
        float cm = mx;
#pragma unroll
        for (int t = 0; t < CHK; t++)
            if (t < cnt) cm = fmaxf(cm, sc[t]);
        float so = __expf(mx - cm);
        den *= so; acc0 *= so; acc1 *= so; acc2 *= so;
        // 4) accumulate chunk (weights independent; FMA chain only)
#pragma unroll
        for (int t = 0; t < CHK; t++) {
            if (t < cnt) {
                float wg = __expf(sc[t] - cm);
                den  += wg;
                acc0 += wg * sv0[t];
                acc1 += wg * sv1[t];
                acc2 += wg * sv2[t];
            }
        }
        mx = cm;
    }

    float inv = 1.f / (den + 1e-16f);
    int c0 = w * CC + lane;
    float v0 = acc0 * inv + bias[c0];
    float v1 = acc1 * inv + bias[c0 + 32];
    float v2 = acc2 * inv + bias[c0 + 64];

    // block LayerNorm over DD=384, then ELU
    __shared__ float rs[4], rq[4];
    float sm = v0 + v1 + v2;
    float sq = v0 * v0 + v1 * v1 + v2 * v2;
    sm = wsum(sm); sq = wsum(sq);
    if (lane == 0) { rs[w] = sm; rq[w] = sq; }
    __syncthreads();
    float S = rs[0] + rs[1] + rs[2] + rs[3];
    float Q = rq[0] + rq[1] + rq[2] + rq[3];
    float mean = S * (1.0f / DD);
    float var  = Q * (1.0f / DD) - mean * mean;
    float rinv = rsqrtf(var + 1e-5f);

    float* orow = out + (size_t)node * DD;
    float y0 = (v0 - mean) * rinv * gamma[c0]      + beta[c0];
    float y1 = (v1 - mean) * rinv * gamma[c0 + 32] + beta[c0 + 32];
    float y2 = (v2 - mean) * rinv * gamma[c0 + 64] + beta[c0 + 64];
    orow[c0]      = (y0 > 0.f) ? y0 : (__expf(y0) - 1.f);
    orow[c0 + 32] = (y1 > 0.f) ? y1 : (__expf(y1) - 1.f);
    orow[c0 + 64] = (y2 > 0.f) ? y2 : (__expf(y2) - 1.f);
}

// ---------------- classifier tail: relu(t1+bc1) -> LN(96) -> @Wc2 + bc2
__global__ __launch_bounds__(128) void cls_k(const float* __restrict__ t1,
                                             const float* __restrict__ bc1,
                                             const float* __restrict__ gc,
                                             const float* __restrict__ bec,
                                             const float* __restrict__ Wc2,
                                             const float* __restrict__ bc2,
                                             float* __restrict__ out) {
    const int node = blockIdx.x;
    const int t = threadIdx.x, w = t >> 5, lane = t & 31;
    __shared__ float z[CC];
    __shared__ float w2[CC * NCLS];
    __shared__ float rs[4], rq[4];

    for (int i = t; i < CC * NCLS; i += 128) w2[i] = Wc2[i];

    float v = 0.f;
    if (t < CC) v = fmaxf(t1[(size_t)node * CC + t] + bc1[t], 0.f);

    float sm = wsum(v), sq = wsum(v * v);
    if (lane == 0) { rs[w] = sm; rq[w] = sq; }
    __syncthreads();
    float S = rs[0] + rs[1] + rs[2] + rs[3];
    float Q = rq[0] + rq[1] + rq[2] + rq[3];
    float mean = S * (1.0f / CC);
    float var  = Q * (1.0f / CC) - mean * mean;
    float rinv = rsqrtf(var + 1e-5f);
    if (t < CC) z[t] = (v - mean) * rinv * gc[t] + bec[t];
    __syncthreads();

    if (t < NCLS) {
        float o = bc2[t];
#pragma unroll 8
        for (int k = 0; k < CC; k++) o = fmaf(z[k], w2[k * NCLS + t], o);
        out[(size_t)node * NCLS + t] = o;
    }
}

// ---------------- launch ----------------
extern "C" void kernel_launch(void* const* d_in, const int* in_sizes, int n_in,
                              void* d_out, int out_size) {
    const float* x   = (const float*)d_in[0];
    const int*   ei  = (const int*)d_in[1];
    const float* Wsrc[3] = {(const float*)d_in[2],  (const float*)d_in[8],  (const float*)d_in[14]};
    const float* Wdst[3] = {(const float*)d_in[3],  (const float*)d_in[9],  (const float*)d_in[15]};
    const float* attp[3] = {(const float*)d_in[4],  (const float*)d_in[10], (const float*)d_in[16]};
    const float* bb[3]   = {(const float*)d_in[5],  (const float*)d_in[11], (const float*)d_in[17]};
    const float* gg[3]   = {(const float*)d_in[6],  (const float*)d_in[12], (const float*)d_in[18]};
    const float* be[3]   = {(const float*)d_in[7],  (const float*)d_in[13], (const float*)d_in[19]};
    const float* Wc1 = (const float*)d_in[20];
    const float* bc1 = (const float*)d_in[21];
    const float* gc  = (const float*)d_in[22];
    const float* bec = (const float*)d_in[23];
    const float* Wc2 = (const float*)d_in[24];
    const float* bc2 = (const float*)d_in[25];
    float* out = (float*)d_out;

    float *xs, *xd, *h, *t1;
    int *off, *cur, *eid, *csrc;
    cudaGetSymbolAddress((void**)&xs,   g_xs);
    cudaGetSymbolAddress((void**)&xd,   g_xd);
    cudaGetSymbolAddress((void**)&h,    g_h);
    cudaGetSymbolAddress((void**)&t1,   g_t1);
    cudaGetSymbolAddress((void**)&off,  g_off);
    cudaGetSymbolAddress((void**)&cur,  g_cur);
    cudaGetSymbolAddress((void**)&eid,  g_eid);
    cudaGetSymbolAddress((void**)&csrc, g_csrc);

    const int* src = ei;
    const int* dst = ei + EE;

    // CSR build (deterministic)
    cudaMemsetAsync(cur, 0, NN * sizeof(int));
    hist_k<<<(EE + 255) / 256, 256>>>(dst, cur);
    scan_k<<<1, 1024>>>(cur, off, cur);
    scatter_k<<<(EE + 255) / 256, 256>>>(dst, cur, eid);
    sortsrc_k<<<(NN + 127) / 128, 128>>>(src, off, eid, csrc);

    // 3 GATv2 layers
    const float* hin = x;
    int kin = FIN;
    for (int l = 0; l < 3; l++) {
        dim3 g1(DD / 128, (NN + 127) / 128);
        gemm_tc<<<g1, 256>>>(hin, Wsrc[l], xs, NN, kin, DD);
        gemm_tc<<<g1, 256>>>(hin, Wdst[l], xd, NN, kin, DD);
        gat_k<<<NN, 128>>>(xs, xd, attp[l], bb[l], gg[l], be[l], off, csrc, h);
        hin = h;
        kin = DD;
    }

    // classifier
    dim3 g2(1, (NN + 127) / 128);
    gemm_tc<<<g2, 256>>>(h, Wc1, t1, NN, DD, CC);
    cls_k<<<NN, 128>>>(t1, bc1, gc, bec, Wc2, bc2, out);
}

// round 6
// speedup vs baseline: 1.1040x; 1.1040x over previous
#include <cuda_runtime.h>
#include <cstdint>

#define NN    50000
#define EE    800000
#define FIN   80
#define HH    4
#define CC    96
#define DD    384
#define NCLS  20

// ---------------- device scratch (no allocations allowed) ----------------
__device__ float g_xs[(size_t)NN * DD];
__device__ float g_xd[(size_t)NN * DD];
__device__ float g_h [(size_t)NN * DD];
__device__ float g_t1[(size_t)NN * CC];
__device__ int   g_off[NN + 1];
__device__ int   g_cur[NN];
__device__ int   g_eid[EE];
__device__ int   g_csrc[EE];

// ---------------- CSR build ----------------
__global__ void hist_k(const int* __restrict__ dst, int* __restrict__ cnt) {
    int i = blockIdx.x * blockDim.x + threadIdx.x;
    if (i < EE) atomicAdd(&cnt[dst[i]], 1);
}

// warp-shuffle scan; writes exclusive offsets to off AND cur
__global__ void scan_k(const int* __restrict__ cnt, int* __restrict__ off,
                       int* __restrict__ cur) {
    __shared__ int wsums[32];
    __shared__ int carry_s;
    const int t = threadIdx.x, lane = t & 31, wp = t >> 5;
    if (t == 0) carry_s = 0;
    __syncthreads();
    for (int base = 0; base < NN; base += 1024) {
        int i = base + t;
        int v = (i < NN) ? cnt[i] : 0;
        int x = v;
#pragma unroll
        for (int o = 1; o < 32; o <<= 1) {
            int y = __shfl_up_sync(0xffffffffu, x, o);
            if (lane >= o) x += y;
        }
        if (lane == 31) wsums[wp] = x;
        __syncthreads();
        if (wp == 0) {
            int ws = wsums[lane];
#pragma unroll
            for (int o = 1; o < 32; o <<= 1) {
                int y = __shfl_up_sync(0xffffffffu, ws, o);
                if (lane >= o) ws += y;
            }
            wsums[lane] = ws;
        }
        __syncthreads();
        int add = (wp > 0) ? wsums[wp - 1] : 0;
        int excl = carry_s + x + add - v;
        if (i < NN) { off[i] = excl; cur[i] = excl; }
        int tot = wsums[31];
        __syncthreads();
        if (t == 0) carry_s += tot;
        __syncthreads();
    }
    if (t == 0) off[NN] = carry_s;
}

__global__ void scatter_k(const int* __restrict__ dst, int* __restrict__ cur,
                          int* __restrict__ eid) {
    int i = blockIdx.x * blockDim.x + threadIdx.x;
    if (i < EE) {
        int d = dst[i];
        int p = atomicAdd(&cur[d], 1);
        eid[p] = i;
    }
}

// deterministic order within segment (sort edge ids), then gather src
__global__ void sortsrc_k(const int* __restrict__ srcArr, const int* __restrict__ off,
                          int* __restrict__ eid, int* __restrict__ csrc) {
    int v = blockIdx.x * blockDim.x + threadIdx.x;
    if (v >= NN) return;
    int s = off[v], e = off[v + 1];
    for (int i = s + 1; i < e; i++) {
        int key = eid[i];
        int j = i - 1;
        while (j >= s && eid[j] > key) { eid[j + 1] = eid[j]; j--; }
        eid[j + 1] = key;
    }
    for (int i = s; i < e; i++) csrc[i] = srcArr[eid[i]];
}

// ---------------- tf32 tensor-core GEMM core: C[M,N] = A[M,K] @ B[K,N] ----------------
// 128x128 CTA tile, 8 warps (64x32 warp tiles), BK=16, mma.m16n8k8.tf32.
// Double-buffered SMEM + software-pipelined global loads, ONE barrier/iter.
__device__ __forceinline__ uint32_t f2tf32(float f) {
    uint32_t r;
    asm("cvt.rna.tf32.f32 %0, %1;" : "=r"(r) : "f"(f));
    return r;
}

struct SmemGemm {
    uint32_t As[2][16][136];
    uint32_t Bs[2][16][136];
};

__device__ __forceinline__ void gemm_core(SmemGemm& sm,
                                          const float* __restrict__ A,
                                          const float* __restrict__ B,
                                          float* __restrict__ C,
                                          int M, int K, int N, int bm, int bn) {
    const int t    = threadIdx.x;
    const int lane = t & 31;
    const int w    = t >> 5;
    const int wm   = (w & 1) * 64;   // warp m offset
    const int wn   = (w >> 1) * 32;  // warp n offset
    const int g    = lane >> 2;      // 0..7
    const int tid4 = lane & 3;       // 0..3

    float acc[4][4][4];
#pragma unroll
    for (int i = 0; i < 4; i++)
#pragma unroll
        for (int j = 0; j < 4; j++)
#pragma unroll
            for (int r = 0; r < 4; r++) acc[i][j][r] = 0.f;

    // global-load mappings
    const int am  = t >> 2;          // 0..63 (+64 for second half)
    const int ak  = (t & 3) * 4;     // k quad
    const int bk  = t >> 5;          // 0..7 (+8)
    const int bn4 = (t & 31) * 4;    // n quad
    const int gn  = bn + bn4;

    const int KT = K >> 4;           // K multiple of 16
    float4 av[2], bv[2];

    // preload tile 0
#pragma unroll
    for (int p = 0; p < 2; p++) {
        int gm = bm + am + p * 64;
        av[p] = make_float4(0.f, 0.f, 0.f, 0.f);
        if (gm < M) av[p] = *(const float4*)(A + (size_t)gm * K + ak);
        bv[p] = make_float4(0.f, 0.f, 0.f, 0.f);
        if (gn < N) bv[p] = *(const float4*)(B + (size_t)(bk + p * 8) * N + gn);
    }

    for (int kt = 0; kt < KT; kt++) {
        const int buf = kt & 1;
        // store current tile (convert to tf32)
#pragma unroll
        for (int p = 0; p < 2; p++) {
            sm.As[buf][ak + 0][am + p * 64] = f2tf32(av[p].x);
            sm.As[buf][ak + 1][am + p * 64] = f2tf32(av[p].y);
            sm.As[buf][ak + 2][am + p * 64] = f2tf32(av[p].z);
            sm.As[buf][ak + 3][am + p * 64] = f2tf32(av[p].w);
            sm.Bs[buf][bk + p * 8][bn4 + 0] = f2tf32(bv[p].x);
            sm.Bs[buf][bk + p * 8][bn4 + 1] = f2tf32(bv[p].y);
            sm.Bs[buf][bk + p * 8][bn4 + 2] = f2tf32(bv[p].z);
            sm.Bs[buf][bk + p * 8][bn4 + 3] = f2tf32(bv[p].w);
        }
        // prefetch next tile (overlaps with this tile's MMAs)
        if (kt + 1 < KT) {
            const int k0 = (kt + 1) << 4;
#pragma unroll
            for (int p = 0; p < 2; p++) {
                int gm = bm + am + p * 64;
                av[p] = make_float4(0.f, 0.f, 0.f, 0.f);
                if (gm < M) av[p] = *(const float4*)(A + (size_t)gm * K + k0 + ak);
                bv[p] = make_float4(0.f, 0.f, 0.f, 0.f);
                if (gn < N) bv[p] = *(const float4*)(B + (size_t)(k0 + bk + p * 8) * N + gn);
            }
        }
        __syncthreads();   // single barrier/iter: double buffer makes it safe

#pragma unroll
        for (int ks = 0; ks < 2; ks++) {
            const int kb = ks * 8;
            uint32_t af[4][4];
#pragma unroll
            for (int mt = 0; mt < 4; mt++) {
                int m = wm + mt * 16;
                af[mt][0] = sm.As[buf][kb + tid4    ][m + g];
                af[mt][1] = sm.As[buf][kb + tid4    ][m + g + 8];
                af[mt][2] = sm.As[buf][kb + tid4 + 4][m + g];
                af[mt][3] = sm.As[buf][kb + tid4 + 4][m + g + 8];
            }
            uint32_t bf[4][2];
#pragma unroll
            for (int nt = 0; nt < 4; nt++) {
                int n = wn + nt * 8;
                bf[nt][0] = sm.Bs[buf][kb + tid4    ][n + g];
                bf[nt][1] = sm.Bs[buf][kb + tid4 + 4][n + g];
            }
#pragma unroll
            for (int mt = 0; mt < 4; mt++)
#pragma unroll
                for (int nt = 0; nt < 4; nt++) {
                    float* c = acc[mt][nt];
                    asm volatile(
                        "mma.sync.aligned.m16n8k8.row.col.f32.tf32.tf32.f32 "
                        "{%0,%1,%2,%3}, {%4,%5,%6,%7}, {%8,%9}, {%0,%1,%2,%3};"
                        : "+f"(c[0]), "+f"(c[1]), "+f"(c[2]), "+f"(c[3])
                        : "r"(af[mt][0]), "r"(af[mt][1]), "r"(af[mt][2]), "r"(af[mt][3]),
                          "r"(bf[nt][0]), "r"(bf[nt][1]));
                }
        }
    }

    // epilogue
#pragma unroll
    for (int mt = 0; mt < 4; mt++) {
#pragma unroll
        for (int nt = 0; nt < 4; nt++) {
            int r0 = bm + wm + mt * 16 + g;
            int c  = bn + wn + nt * 8 + 2 * tid4;
            if (c < N) {
                if (r0 < M)
                    *(float2*)(C + (size_t)r0 * N + c) =
                        make_float2(acc[mt][nt][0], acc[mt][nt][1]);
                if (r0 + 8 < M)
                    *(float2*)(C + (size_t)(r0 + 8) * N + c) =
                        make_float2(acc[mt][nt][2], acc[mt][nt][3]);
            }
        }
    }
}

__global__ __launch_bounds__(256) void gemm_tc(const float* __restrict__ A,
                                               const float* __restrict__ B,
                                               float* __restrict__ C,
                                               int M, int K, int N) {
    __shared__ SmemGemm sm;
    gemm_core(sm, A, B, C, M, K, N, blockIdx.y * 128, blockIdx.x * 128);
}

// fused pair: first nx x-blocks compute A@B0 -> C0, rest compute A@B1 -> C1
__global__ __launch_bounds__(256) void gemm_dual(const float* __restrict__ A,
                                                 const float* __restrict__ B0,
                                                 float* __restrict__ C0,
                                                 const float* __restrict__ B1,
                                                 float* __restrict__ C1,
                                                 int M, int K, int N) {
    __shared__ SmemGemm sm;
    const int nx = N / 128;
    const bool second = (blockIdx.x >= nx);
    const float* B = second ? B1 : B0;
    float*       C = second ? C1 : C0;
    const int bn = (second ? (blockIdx.x - nx) : blockIdx.x) * 128;
    gemm_core(sm, A, B, C, M, K, N, blockIdx.y * 128, bn);
}

// ---------------- helpers ----------------
__device__ __forceinline__ float wsum(float v) {
#pragma unroll
    for (int o = 16; o; o >>= 1) v += __shfl_xor_sync(0xffffffffu, v, o);
    return v;
}

// ---------------- GATv2 layer: attention + softmax + aggregate + bias + LN + ELU
// one block (128 threads) per node; warp w handles head w; online softmax,
// with next-edge prefetch to hide L2 gather latency. (round-3 proven version)
__global__ __launch_bounds__(128) void gat_k(const float* __restrict__ xs,
                                             const float* __restrict__ xd,
                                             const float* __restrict__ att,
                                             const float* __restrict__ bias,
                                             const float* __restrict__ gamma,
                                             const float* __restrict__ beta,
                                             const int* __restrict__ off,
                                             const int* __restrict__ csrc,
                                             float* __restrict__ out) {
    const int node = blockIdx.x;
    const int w    = threadIdx.x >> 5;
    const int lane = threadIdx.x & 31;

    const float* ah = att + w * CC;
    const float a0 = ah[lane], a1 = ah[lane + 32], a2 = ah[lane + 64];

    const float* dr = xd + (size_t)node * DD + w * CC;
    const float d0 = dr[lane], d1 = dr[lane + 32], d2 = dr[lane + 64];

    const int s = off[node], e = off[node + 1];

    float mx = -3.0e38f, den = 0.f;
    float acc0 = 0.f, acc1 = 0.f, acc2 = 0.f;

    if (s < e) {
        int sr = __ldg(&csrc[s]);
        const float* xr = xs + (size_t)sr * DD + w * CC;
        float p0 = xr[lane], p1 = xr[lane + 32], p2 = xr[lane + 64];

        for (int j = s; j < e; j++) {
            float s0 = p0, s1 = p1, s2 = p2;
            if (j + 1 < e) {
                int srn = __ldg(&csrc[j + 1]);
                const float* xn = xs + (size_t)srn * DD + w * CC;
                p0 = xn[lane]; p1 = xn[lane + 32]; p2 = xn[lane + 64];
            }
            float m0 = s0 + d0; m0 = (m0 > 0.f) ? m0 : 0.2f * m0;
            float m1 = s1 + d1; m1 = (m1 > 0.f) ? m1 : 0.2f * m1;
            float m2 = s2 + d2; m2 = (m2 > 0.f) ? m2 : 0.2f * m2;
            float p = a0 * m0 + a1 * m1 + a2 * m2;
            p = wsum(p);                       // e_ij, broadcast to all lanes
            float nm = fmaxf(mx, p);
            float so = __expf(mx - nm);        // rescale old state
            float wg = __expf(p - nm);
            den  = den  * so + wg;
            acc0 = acc0 * so + wg * s0;
            acc1 = acc1 * so + wg * s1;
            acc2 = acc2 * so + wg * s2;
            mx = nm;
        }
    }

    float inv = 1.f / (den + 1e-16f);
    int c0 = w * CC + lane;
    float v0 = acc0 * inv + bias[c0];
    float v1 = acc1 * inv + bias[c0 + 32];
    float v2 = acc2 * inv + bias[c0 + 64];

    // block LayerNorm over DD=384, then ELU
    __shared__ float rs[4], rq[4];
    float sm = v0 + v1 + v2;
    float sq = v0 * v0 + v1 * v1 + v2 * v2;
    sm = wsum(sm); sq = wsum(sq);
    if (lane == 0) { rs[w] = sm; rq[w] = sq; }
    __syncthreads();
    float S = rs[0] + rs[1] + rs[2] + rs[3];
    float Q = rq[0] + rq[1] + rq[2] + rq[3];
    float mean = S * (1.0f / DD);
    float var  = Q * (1.0f / DD) - mean * mean;
    float rinv = rsqrtf(var + 1e-5f);

    float* orow = out + (size_t)node * DD;
    float y0 = (v0 - mean) * rinv * gamma[c0]      + beta[c0];
    float y1 = (v1 - mean) * rinv * gamma[c0 + 32] + beta[c0 + 32];
    float y2 = (v2 - mean) * rinv * gamma[c0 + 64] + beta[c0 + 64];
    orow[c0]      = (y0 > 0.f) ? y0 : (__expf(y0) - 1.f);
    orow[c0 + 32] = (y1 > 0.f) ? y1 : (__expf(y1) - 1.f);
    orow[c0 + 64] = (y2 > 0.f) ? y2 : (__expf(y2) - 1.f);
}

// ---------------- classifier tail: relu(t1+bc1) -> LN(96) -> @Wc2 + bc2
__global__ __launch_bounds__(128) void cls_k(const float* __restrict__ t1,
                                             const float* __restrict__ bc1,
                                             const float* __restrict__ gc,
                                             const float* __restrict__ bec,
                                             const float* __restrict__ Wc2,
                                             const float* __restrict__ bc2,
                                             float* __restrict__ out) {
    const int node = blockIdx.x;
    const int t = threadIdx.x, w = t >> 5, lane = t & 31;
    __shared__ float z[CC];
    __shared__ float w2[CC * NCLS];
    __shared__ float rs[4], rq[4];

    for (int i = t; i < CC * NCLS; i += 128) w2[i] = Wc2[i];

    float v = 0.f;
    if (t < CC) v = fmaxf(t1[(size_t)node * CC + t] + bc1[t], 0.f);

    float sm = wsum(v), sq = wsum(v * v);
    if (lane == 0) { rs[w] = sm; rq[w] = sq; }
    __syncthreads();
    float S = rs[0] + rs[1] + rs[2] + rs[3];
    float Q = rq[0] + rq[1] + rq[2] + rq[3];
    float mean = S * (1.0f / CC);
    float var  = Q * (1.0f / CC) - mean * mean;
    float rinv = rsqrtf(var + 1e-5f);
    if (t < CC) z[t] = (v - mean) * rinv * gc[t] + bec[t];
    __syncthreads();

    if (t < NCLS) {
        float o = bc2[t];
#pragma unroll 8
        for (int k = 0; k < CC; k++) o = fmaf(z[k], w2[k * NCLS + t], o);
        out[(size_t)node * NCLS + t] = o;
    }
}

// ---------------- launch ----------------
extern "C" void kernel_launch(void* const* d_in, const int* in_sizes, int n_in,
                              void* d_out, int out_size) {
    const float* x   = (const float*)d_in[0];
    const int*   ei  = (const int*)d_in[1];
    const float* Wsrc[3] = {(const float*)d_in[2],  (const float*)d_in[8],  (const float*)d_in[14]};
    const float* Wdst[3] = {(const float*)d_in[3],  (const float*)d_in[9],  (const float*)d_in[15]};
    const float* attp[3] = {(const float*)d_in[4],  (const float*)d_in[10], (const float*)d_in[16]};
    const float* bb[3]   = {(const float*)d_in[5],  (const float*)d_in[11], (const float*)d_in[17]};
    const float* gg[3]   = {(const float*)d_in[6],  (const float*)d_in[12], (const float*)d_in[18]};
    const float* be[3]   = {(const float*)d_in[7],  (const float*)d_in[13], (const float*)d_in[19]};
    const float* Wc1 = (const float*)d_in[20];
    const float* bc1 = (const float*)d_in[21];
    const float* gc  = (const float*)d_in[22];
    const float* bec = (const float*)d_in[23];
    const float* Wc2 = (const float*)d_in[24];
    const float* bc2 = (const float*)d_in[25];
    float* out = (float*)d_out;

    float *xs, *xd, *h, *t1;
    int *off, *cur, *eid, *csrc;
    cudaGetSymbolAddress((void**)&xs,   g_xs);
    cudaGetSymbolAddress((void**)&xd,   g_xd);
    cudaGetSymbolAddress((void**)&h,    g_h);
    cudaGetSymbolAddress((void**)&t1,   g_t1);
    cudaGetSymbolAddress((void**)&off,  g_off);
    cudaGetSymbolAddress((void**)&cur,  g_cur);
    cudaGetSymbolAddress((void**)&eid,  g_eid);
    cudaGetSymbolAddress((void**)&csrc, g_csrc);

    const int* src = ei;
    const int* dst = ei + EE;

    dim3 g1(DD / 128, (NN + 127) / 128);       // 3 x 391
    dim3 gd(2 * (DD / 128), (NN + 127) / 128); // 6 x 391

    // CSR build start (gat needs it; gemms don't)
    cudaMemsetAsync(cur, 0, NN * sizeof(int));
    hist_k<<<(EE + 255) / 256, 256>>>(dst, cur);
    scan_k<<<1, 1024>>>(cur, off, cur);
    scatter_k<<<(EE + 255) / 256, 256>>>(dst, cur, eid);

    // layer-0 GEMMs placed at stream launch slots 5-6 so ncu's fixed
    // profiling window (-s 5 -c 1) lands on gemm_tc, not a CSR kernel.
    gemm_tc<<<g1, 256>>>(x, Wsrc[0], xs, NN, FIN, DD);
    gemm_tc<<<g1, 256>>>(x, Wdst[0], xd, NN, FIN, DD);

    sortsrc_k<<<(NN + 127) / 128, 128>>>(src, off, eid, csrc);

    // layer 0 aggregate
    gat_k<<<NN, 128>>>(xs, xd, attp[0], bb[0], gg[0], be[0], off, csrc, h);

    // layers 1..2 (fused GEMM pair)
    for (int l = 1; l < 3; l++) {
        gemm_dual<<<gd, 256>>>(h, Wsrc[l], xs, Wdst[l], xd, NN, DD, DD);
        gat_k<<<NN, 128>>>(xs, xd, attp[l], bb[l], gg[l], be[l], off, csrc, h);
    }

    // classifier
    dim3 g2(1, (NN + 127) / 128);
    gemm_tc<<<g2, 256>>>(h, Wc1, t1, NN, DD, CC);
    cls_k<<<NN, 128>>>(t1, bc1, gc, bec, Wc2, bc2, out);
}